// round 1
// baseline (speedup 1.0000x reference)
#include <cuda_runtime.h>
#include <math.h>

// ChamferLoss: bs=4, npts=4096, dim=3.
// result = mean_i min_j sqrt(eps + ||x_j - y_i||^2)   [min2: per-y nearest x]
//        + mean_j min_i sqrt(eps + ||x_j - y_i||^2)   [min1: per-x nearest y]
// sqrt is monotone -> minimize squared distance, sqrt once per point.

#define NPTS 4096
#define BS   4
#define QPB  128                 // queries per block == threads per block
#define QT   (NPTS / QPB)        // 32 query tiles
#define NBLK (QT * BS * 2)       // 256 partial sums

__device__ float g_partial[NBLK];

__global__ __launch_bounds__(QPB) void chamfer_min_kernel(
    const float* __restrict__ x, const float* __restrict__ y)
{
    // Negated reference coords, SoA, viewed as packed float2 (two refs per 64b).
    __shared__ float s[3 * NPTS];   // 49152 bytes (exactly 48KB static)

    const int tid = threadIdx.x;
    const int qt  = blockIdx.x;
    const int b   = blockIdx.y;
    const int dir = blockIdx.z;     // 0: query=x ref=y (min1), 1: query=y ref=x (min2)

    const float* __restrict__ q = (dir == 0) ? x : y;
    const float* __restrict__ r = (dir == 0) ? y : x;
    const float* __restrict__ rb = r + (size_t)b * NPTS * 3;

    // Stage negated reference set into shared (SoA).
    #pragma unroll 4
    for (int i = tid; i < NPTS; i += QPB) {
        float r0 = rb[3 * i + 0];
        float r1 = rb[3 * i + 1];
        float r2 = rb[3 * i + 2];
        s[i]            = -r0;
        s[NPTS + i]     = -r1;
        s[2 * NPTS + i] = -r2;
    }

    // Load this thread's query point, broadcast-pack each coord into f32x2.
    const int qi = qt * QPB + tid;
    const float* __restrict__ qp = q + ((size_t)b * NPTS + qi) * 3;
    const float qx = qp[0], qy = qp[1], qz = qp[2];
    unsigned long long q0, q1, q2;
    asm("mov.b64 %0, {%1, %1};" : "=l"(q0) : "r"(__float_as_uint(qx)));
    asm("mov.b64 %0, {%1, %1};" : "=l"(q1) : "r"(__float_as_uint(qy)));
    asm("mov.b64 %0, {%1, %1};" : "=l"(q2) : "r"(__float_as_uint(qz)));

    __syncthreads();

    const unsigned long long* __restrict__ p0 = (const unsigned long long*)(s);
    const unsigned long long* __restrict__ p1 = (const unsigned long long*)(s + NPTS);
    const unsigned long long* __restrict__ p2 = (const unsigned long long*)(s + 2 * NPTS);

    float m = 3.402823466e+38f;

    #pragma unroll 8
    for (int k = 0; k < NPTS / 2; ++k) {
        unsigned long long nb0 = p0[k];   // (-rx[2k], -rx[2k+1])  via LDS.64 broadcast
        unsigned long long nb1 = p1[k];
        unsigned long long nb2 = p2[k];
        unsigned long long d0, d1, d2, sq;
        asm("add.rn.f32x2 %0, %1, %2;" : "=l"(d0) : "l"(q0), "l"(nb0));
        asm("add.rn.f32x2 %0, %1, %2;" : "=l"(d1) : "l"(q1), "l"(nb1));
        asm("add.rn.f32x2 %0, %1, %2;" : "=l"(d2) : "l"(q2), "l"(nb2));
        asm("mul.rn.f32x2 %0, %1, %1;" : "=l"(sq) : "l"(d0));
        asm("fma.rn.f32x2 %0, %1, %1, %0;" : "+l"(sq) : "l"(d1));
        asm("fma.rn.f32x2 %0, %1, %1, %0;" : "+l"(sq) : "l"(d2));
        unsigned int lo, hi;
        asm("mov.b64 {%0, %1}, %2;" : "=r"(lo), "=r"(hi) : "l"(sq));
        m = fminf(m, __uint_as_float(lo));
        m = fminf(m, __uint_as_float(hi));
    }

    float v = sqrtf(1e-6f + m);

    // Block-sum (deterministic): warp shuffle reduce, then 4 warp sums via smem.
    #pragma unroll
    for (int off = 16; off; off >>= 1)
        v += __shfl_down_sync(0xFFFFFFFFu, v, off);

    __syncthreads();                 // everyone done reading s; reuse it
    if ((tid & 31) == 0) s[tid >> 5] = v;
    __syncthreads();
    if (tid == 0) {
        float t = s[0] + s[1] + s[2] + s[3];
        g_partial[(dir * BS + b) * QT + qt] = t;
    }
}

__global__ __launch_bounds__(256) void chamfer_finalize_kernel(float* __restrict__ out)
{
    __shared__ float sh[8];
    const int tid = threadIdx.x;     // 256 threads == NBLK
    float v = g_partial[tid];
    #pragma unroll
    for (int off = 16; off; off >>= 1)
        v += __shfl_down_sync(0xFFFFFFFFu, v, off);
    if ((tid & 31) == 0) sh[tid >> 5] = v;
    __syncthreads();
    if (tid == 0) {
        float t = 0.f;
        #pragma unroll
        for (int i = 0; i < 8; ++i) t += sh[i];
        out[0] = t / (float)(BS * NPTS);   // (S1 + S2) / 16384 == mean1 + mean2
    }
}

extern "C" void kernel_launch(void* const* d_in, const int* in_sizes, int n_in,
                              void* d_out, int out_size)
{
    const float* x = (const float*)d_in[0];
    const float* y = (const float*)d_in[1];
    float* out = (float*)d_out;

    dim3 grid(QT, BS, 2);
    chamfer_min_kernel<<<grid, QPB>>>(x, y);
    chamfer_finalize_kernel<<<1, 256>>>(out);
}